// round 1
// baseline (speedup 1.0000x reference)
#include <cuda_runtime.h>
#include <cuda_bf16.h>
#include <math.h>

// Problem constants
#define HEADS   12
#define DMODEL  768
#define HDIM    64
#define BATCH   2
#define SEQ     2048
#define ROWS    (BATCH * SEQ)          // 4096
#define BH      (BATCH * HEADS)        // 24

static const long long OUT_ELEMS = (long long)BATCH * SEQ * DMODEL;            // 3,145,728
static const long long W_ELEMS   = (long long)BATCH * HEADS * SEQ * SEQ;       // 100,663,296

// Scratch (device globals: allocation-free)
__device__ float g_qw[ROWS * DMODEL];   // [b][h][s][dh]
__device__ float g_kw[ROWS * DMODEL];
__device__ float g_vw[ROWS * DMODEL];
__device__ float g_ctx[ROWS * DMODEL]; // [b][s][d]
__device__ float g_wscratch[(long long)BATCH * HEADS * SEQ * SEQ]; // fallback weights
__device__ float g_oscratch[ROWS * DMODEL];                        // fallback out

// ---------------------------------------------------------------------------
// Tiled SGEMM: C = A[M,K] @ W[N,K]^T + bias, BM=BN=64, BK=16, 256 thr, 4x4 micro
// mode 0: scatter C to head layout [b][h][s][dh] (qkv projections)
// mode 1: plain row-major C[M,N]  (output projection)
// ---------------------------------------------------------------------------
__global__ void gemm_xwT_kernel(const float* __restrict__ A,
                                const float* __restrict__ W,
                                const float* __restrict__ bias,
                                float* __restrict__ C,
                                int M, int N, int K, int mode)
{
    __shared__ float As[16][68];
    __shared__ float Ws[16][68];
    const int tid = threadIdx.x;
    const int m0 = blockIdx.x * 64;
    const int n0 = blockIdx.y * 64;
    const int ty = tid >> 4;       // 0..15
    const int tx = tid & 15;       // 0..15

    float acc[4][4] = {};

    const int lr  = tid >> 2;           // 0..63 (row within tile)
    const int lk4 = (tid & 3) * 4;      // 0,4,8,12

    for (int k0 = 0; k0 < K; k0 += 16) {
        float4 va = *(const float4*)&A[(size_t)(m0 + lr) * K + k0 + lk4];
        float4 vw = *(const float4*)&W[(size_t)(n0 + lr) * K + k0 + lk4];
        As[lk4 + 0][lr] = va.x; As[lk4 + 1][lr] = va.y;
        As[lk4 + 2][lr] = va.z; As[lk4 + 3][lr] = va.w;
        Ws[lk4 + 0][lr] = vw.x; Ws[lk4 + 1][lr] = vw.y;
        Ws[lk4 + 2][lr] = vw.z; Ws[lk4 + 3][lr] = vw.w;
        __syncthreads();
#pragma unroll
        for (int kk = 0; kk < 16; ++kk) {
            float4 a4 = *(const float4*)&As[kk][ty * 4];
            float4 b4 = *(const float4*)&Ws[kk][tx * 4];
            float av[4] = {a4.x, a4.y, a4.z, a4.w};
            float bv[4] = {b4.x, b4.y, b4.z, b4.w};
#pragma unroll
            for (int i = 0; i < 4; ++i)
#pragma unroll
                for (int j = 0; j < 4; ++j)
                    acc[i][j] = fmaf(av[i], bv[j], acc[i][j]);
        }
        __syncthreads();
    }

#pragma unroll
    for (int i = 0; i < 4; ++i) {
        int m = m0 + ty * 4 + i;
#pragma unroll
        for (int j = 0; j < 4; ++j) {
            int n = n0 + tx * 4 + j;
            float v = acc[i][j] + bias[n];
            if (mode == 0) {
                int b = m >> 11, s = m & 2047;
                int h = n >> 6,  dh = n & 63;
                C[(((size_t)(b * HEADS + h)) * SEQ + s) * HDIM + dh] = v;
            } else {
                C[(size_t)m * N + n] = v;
            }
        }
    }
}

// ---------------------------------------------------------------------------
// Scores: per (b,h): S = (Qh @ Kh^T) * 0.125, masked -> -inf. Written
// unnormalized into the weights buffer (softmax pass normalizes in place).
// ---------------------------------------------------------------------------
__global__ void scores_kernel(const float* __restrict__ qw,
                              const float* __restrict__ kw,
                              const float* __restrict__ mask,
                              float* __restrict__ wout)
{
    const int bh = blockIdx.z;
    const float* A = qw + (size_t)bh * SEQ * HDIM;
    const float* B = kw + (size_t)bh * SEQ * HDIM;
    float* C = wout + (size_t)bh * SEQ * SEQ;
    const int bidx = bh / HEADS;

    __shared__ float As[16][68];
    __shared__ float Bs[16][68];
    const int tid = threadIdx.x;
    const int m0 = blockIdx.x * 64;
    const int n0 = blockIdx.y * 64;
    const int ty = tid >> 4, tx = tid & 15;

    float acc[4][4] = {};
    const int lr  = tid >> 2;
    const int lk4 = (tid & 3) * 4;

    for (int k0 = 0; k0 < HDIM; k0 += 16) {
        float4 va = *(const float4*)&A[(size_t)(m0 + lr) * HDIM + k0 + lk4];
        float4 vb = *(const float4*)&B[(size_t)(n0 + lr) * HDIM + k0 + lk4];
        As[lk4 + 0][lr] = va.x; As[lk4 + 1][lr] = va.y;
        As[lk4 + 2][lr] = va.z; As[lk4 + 3][lr] = va.w;
        Bs[lk4 + 0][lr] = vb.x; Bs[lk4 + 1][lr] = vb.y;
        Bs[lk4 + 2][lr] = vb.z; Bs[lk4 + 3][lr] = vb.w;
        __syncthreads();
#pragma unroll
        for (int kk = 0; kk < 16; ++kk) {
            float4 a4 = *(const float4*)&As[kk][ty * 4];
            float4 b4 = *(const float4*)&Bs[kk][tx * 4];
            float av[4] = {a4.x, a4.y, a4.z, a4.w};
            float bv[4] = {b4.x, b4.y, b4.z, b4.w};
#pragma unroll
            for (int i = 0; i < 4; ++i)
#pragma unroll
                for (int j = 0; j < 4; ++j)
                    acc[i][j] = fmaf(av[i], bv[j], acc[i][j]);
        }
        __syncthreads();
    }

#pragma unroll
    for (int i = 0; i < 4; ++i) {
        int m = m0 + ty * 4 + i;
#pragma unroll
        for (int j = 0; j < 4; ++j) {
            int n = n0 + tx * 4 + j;
            float mv = mask[bidx * SEQ + n];
            float v = (mv != 0.0f) ? -INFINITY : acc[i][j] * 0.125f;
            C[(size_t)m * SEQ + n] = v;
        }
    }
}

// ---------------------------------------------------------------------------
// Row softmax in place: one block (256 thr) per row of 2048
// ---------------------------------------------------------------------------
__global__ void softmax_kernel(float* __restrict__ w)
{
    __shared__ float red[8];
    const size_t row = blockIdx.x;
    float* p = w + row * SEQ;
    const int tid = threadIdx.x;
    const int lane = tid & 31, wid = tid >> 5;

    float4 v0 = ((const float4*)p)[tid];
    float4 v1 = ((const float4*)p)[tid + 256];

    float mx = fmaxf(fmaxf(fmaxf(v0.x, v0.y), fmaxf(v0.z, v0.w)),
                     fmaxf(fmaxf(v1.x, v1.y), fmaxf(v1.z, v1.w)));
#pragma unroll
    for (int off = 16; off > 0; off >>= 1)
        mx = fmaxf(mx, __shfl_xor_sync(0xffffffffu, mx, off));
    if (lane == 0) red[wid] = mx;
    __syncthreads();
    if (tid == 0) {
        float m = red[0];
#pragma unroll
        for (int i = 1; i < 8; ++i) m = fmaxf(m, red[i]);
        red[0] = m;
    }
    __syncthreads();
    mx = red[0];

    float e[8];
    e[0] = __expf(v0.x - mx); e[1] = __expf(v0.y - mx);
    e[2] = __expf(v0.z - mx); e[3] = __expf(v0.w - mx);
    e[4] = __expf(v1.x - mx); e[5] = __expf(v1.y - mx);
    e[6] = __expf(v1.z - mx); e[7] = __expf(v1.w - mx);
    float sum = 0.0f;
#pragma unroll
    for (int i = 0; i < 8; ++i) sum += e[i];
#pragma unroll
    for (int off = 16; off > 0; off >>= 1)
        sum += __shfl_xor_sync(0xffffffffu, sum, off);
    __syncthreads();
    if (lane == 0) red[wid] = sum;
    __syncthreads();
    if (tid == 0) {
        float s = 0.0f;
#pragma unroll
        for (int i = 0; i < 8; ++i) s += red[i];
        red[0] = s;
    }
    __syncthreads();
    float inv = 1.0f / red[0];

    float4 o0, o1;
    o0.x = e[0] * inv; o0.y = e[1] * inv; o0.z = e[2] * inv; o0.w = e[3] * inv;
    o1.x = e[4] * inv; o1.y = e[5] * inv; o1.z = e[6] * inv; o1.w = e[7] * inv;
    ((float4*)p)[tid]       = o0;
    ((float4*)p)[tid + 256] = o1;
}

// ---------------------------------------------------------------------------
// ctx = weights[2048,2048] @ vw[2048,64], per (b,h). Result scattered to
// [b][s][h*64+dh] so final projection reads a plain [4096,768] matrix.
// ---------------------------------------------------------------------------
__global__ void ctx_kernel(const float* __restrict__ w,
                           const float* __restrict__ vw,
                           float* __restrict__ ctx)
{
    const int bh = blockIdx.z;
    const int b = bh / HEADS, h = bh % HEADS;
    const float* A = w  + (size_t)bh * SEQ * SEQ;   // [2048][2048]
    const float* B = vw + (size_t)bh * SEQ * HDIM;  // [2048][64] (K-rows, N-cols)

    __shared__ float As[16][68];
    __shared__ float Bs[16][68];
    const int tid = threadIdx.x;
    const int m0 = blockIdx.x * 64;
    const int ty = tid >> 4, tx = tid & 15;

    float acc[4][4] = {};
    const int lr  = tid >> 2;
    const int lk4 = (tid & 3) * 4;
    const int lkb = tid >> 4;           // 0..15
    const int ln4 = (tid & 15) * 4;     // 0..60

    for (int k0 = 0; k0 < SEQ; k0 += 16) {
        float4 va = *(const float4*)&A[(size_t)(m0 + lr) * SEQ + k0 + lk4];
        As[lk4 + 0][lr] = va.x; As[lk4 + 1][lr] = va.y;
        As[lk4 + 2][lr] = va.z; As[lk4 + 3][lr] = va.w;
        float4 vb = *(const float4*)&B[(size_t)(k0 + lkb) * HDIM + ln4];
        *(float4*)&Bs[lkb][ln4] = vb;
        __syncthreads();
#pragma unroll
        for (int kk = 0; kk < 16; ++kk) {
            float4 a4 = *(const float4*)&As[kk][ty * 4];
            float4 b4 = *(const float4*)&Bs[kk][tx * 4];
            float av[4] = {a4.x, a4.y, a4.z, a4.w};
            float bv[4] = {b4.x, b4.y, b4.z, b4.w};
#pragma unroll
            for (int i = 0; i < 4; ++i)
#pragma unroll
                for (int j = 0; j < 4; ++j)
                    acc[i][j] = fmaf(av[i], bv[j], acc[i][j]);
        }
        __syncthreads();
    }

#pragma unroll
    for (int i = 0; i < 4; ++i) {
        int s = m0 + ty * 4 + i;
#pragma unroll
        for (int j = 0; j < 4; ++j) {
            int dh = tx * 4 + j;
            ctx[((size_t)(b * SEQ + s)) * DMODEL + h * HDIM + dh] = acc[i][j];
        }
    }
}

// ---------------------------------------------------------------------------
extern "C" void kernel_launch(void* const* d_in, const int* in_sizes, int n_in,
                              void* d_out, int out_size)
{
    const float* q    = (const float*)d_in[0];
    const float* k    = (const float*)d_in[1];
    const float* v    = (const float*)d_in[2];
    const float* mask = (const float*)d_in[3];
    const float* Wq   = (const float*)d_in[4];
    const float* bq   = (const float*)d_in[5];
    const float* Wk   = (const float*)d_in[6];
    const float* bk   = (const float*)d_in[7];
    const float* Wv   = (const float*)d_in[8];
    const float* bv   = (const float*)d_in[9];
    const float* Wo   = (const float*)d_in[10];
    const float* bo   = (const float*)d_in[11];

    float *p_qw, *p_kw, *p_vw, *p_ctx, *p_wsc, *p_osc;
    cudaGetSymbolAddress((void**)&p_qw,  g_qw);
    cudaGetSymbolAddress((void**)&p_kw,  g_kw);
    cudaGetSymbolAddress((void**)&p_vw,  g_vw);
    cudaGetSymbolAddress((void**)&p_ctx, g_ctx);
    cudaGetSymbolAddress((void**)&p_wsc, g_wscratch);
    cudaGetSymbolAddress((void**)&p_osc, g_oscratch);

    float* outp;
    float* wp;
    long long osz = (long long)out_size;
    if (osz >= OUT_ELEMS + W_ELEMS) {          // (out, weights) concatenated
        outp = (float*)d_out;
        wp   = (float*)d_out + OUT_ELEMS;
    } else if (osz == W_ELEMS) {               // weights only
        wp   = (float*)d_out;
        outp = p_osc;
    } else {                                   // out only
        outp = (float*)d_out;
        wp   = p_wsc;
    }

    dim3 blk(256);

    // Q/K/V projections -> head layout
    dim3 gProj(ROWS / 64, DMODEL / 64);
    gemm_xwT_kernel<<<gProj, blk>>>(q, Wq, bq, p_qw, ROWS, DMODEL, DMODEL, 0);
    gemm_xwT_kernel<<<gProj, blk>>>(k, Wk, bk, p_kw, ROWS, DMODEL, DMODEL, 0);
    gemm_xwT_kernel<<<gProj, blk>>>(v, Wv, bv, p_vw, ROWS, DMODEL, DMODEL, 0);

    // Scores (masked, scaled, unnormalized) into weights buffer
    dim3 gSc(SEQ / 64, SEQ / 64, BH);
    scores_kernel<<<gSc, blk>>>(p_qw, p_kw, mask, wp);

    // Row softmax in place (weights become final output values)
    softmax_kernel<<<BH * SEQ, blk>>>(wp);

    // ctx = P @ V  -> [b][s][d]
    dim3 gCtx(SEQ / 64, 1, BH);
    ctx_kernel<<<gCtx, blk>>>(wp, p_vw, p_ctx);

    // Output projection
    gemm_xwT_kernel<<<gProj, blk>>>(p_ctx, Wo, bo, outp, ROWS, DMODEL, DMODEL, 1);
}

// round 2
// speedup vs baseline: 1.6978x; 1.6978x over previous
#include <cuda_runtime.h>
#include <cuda_bf16.h>
#include <math.h>
#include <stdint.h>

#define HEADS   12
#define DMODEL  768
#define HDIM    64
#define BATCH   2
#define SEQ     2048
#define ROWS    (BATCH * SEQ)          // 4096
#define BH      (BATCH * HEADS)        // 24

static const long long OUT_ELEMS = (long long)ROWS * DMODEL;             // 3,145,728
static const long long W_ELEMS   = (long long)BH * SEQ * SEQ;            // 100,663,296

// Scratch (device globals: allocation-free)
__device__ float g_qw [ROWS * DMODEL];   // [b][h][s][dh]
__device__ float g_kw [ROWS * DMODEL];   // [b][h][s][dh]
__device__ float g_vwT[ROWS * DMODEL];   // [b][h][dh][s]  (transposed for PV gemm)
__device__ float g_ctx[ROWS * DMODEL];   // [b][s][d]
__device__ float g_wscratch[(long long)BH * SEQ * SEQ];
__device__ float g_oscratch[ROWS * DMODEL];

struct QKVArgs {
    const float* A[3];
    const float* W[3];
    const float* b[3];
    float*       C[3];
};

__device__ __forceinline__ void mma16816(float* c,
                                         uint32_t a0, uint32_t a1, uint32_t a2, uint32_t a3,
                                         uint32_t b0, uint32_t b1)
{
    asm volatile(
        "mma.sync.aligned.m16n8k16.row.col.f32.bf16.bf16.f32 "
        "{%0,%1,%2,%3}, {%4,%5,%6,%7}, {%8,%9}, {%0,%1,%2,%3};\n"
        : "+f"(c[0]), "+f"(c[1]), "+f"(c[2]), "+f"(c[3])
        : "r"(a0), "r"(a1), "r"(a2), "r"(a3), "r"(b0), "r"(b1));
}

// ---------------------------------------------------------------------------
// Generic C = A[M,K] @ B[N,K]^T tile kernel, bf16x3 split (fp32-accurate),
// fp32 in/out. BM=128 fixed; BN/warp-shape/epilogue via template.
// MODE 1: plain row-major C (ldc=DMODEL) + bias           (output projection)
// MODE 3: scores epilogue: *0.125, mask!=0 -> -inf, C per-z [SEQ,SEQ]
// MODE 4: ctx epilogue: scatter to [b, s, h*64+dh]
// MODE 5: fused QKV projection, z selects {q,k,v}; z<2 head-scatter, z=2
//         transposed scatter into vwT
// ---------------------------------------------------------------------------
template<int BN, int MF, int NF, int WM, int WN, int MODE>
__global__ void __launch_bounds__(256)
mma_gemm(const float* __restrict__ Ag, int lda, long long Az,
         const float* __restrict__ Bg, int ldb, long long Bz,
         float* __restrict__ Cg,
         const float* __restrict__ biasg,
         const float* __restrict__ maskg,
         int K, QKVArgs qa)
{
    constexpr int BM  = 128;
    constexpr int BKP = 18;                       // padded bf16 k-stride
    constexpr int LB4 = (BN * 16) / (256 * 4);    // float4 per thread for B (1 or 2)
    static_assert(WM * WN == 8, "8 warps");
    static_assert(WM * MF * 16 == BM, "BM");
    static_assert(WN * NF * 8  == BN, "BN");

    __shared__ __nv_bfloat16 Ah[2][BM][BKP], Al[2][BM][BKP];
    __shared__ __nv_bfloat16 Bh[2][BN][BKP], Bl[2][BN][BKP];

    const int tid  = threadIdx.x;
    const int wid  = tid >> 5;
    const int lane = tid & 31;
    const int g    = lane >> 2;     // 0..7
    const int t    = lane & 3;      // 0..3
    const int wm   = wid % WM;
    const int wn   = wid / WM;
    const int m0   = blockIdx.x * BM;
    const int n0   = blockIdx.y * BN;
    const int z    = blockIdx.z;

    const float* Ap;
    const float* Bp;
    const float* biasp = biasg;
    if (MODE == 5) { Ap = qa.A[z]; Bp = qa.W[z]; biasp = qa.b[z]; }
    else           { Ap = Ag + (long long)z * Az; Bp = Bg + (long long)z * Bz; }

    // loader indices: A tile is 128x16 floats -> 2 float4/thread
    const int ar = tid >> 1;
    const int ac = (tid & 1) * 8;
    const int br = (LB4 == 2) ? (tid >> 1) : (tid >> 2);
    const int bc = (LB4 == 2) ? ((tid & 1) * 8) : ((tid & 3) * 4);

    float acc[MF][NF][4] = {};

    float4 fa0, fa1, fb0, fb1;

    auto fetch = [&](int k0) {
        const float* arow = Ap + (size_t)(m0 + ar) * lda + k0 + ac;
        fa0 = *(const float4*)arow;
        fa1 = *(const float4*)(arow + 4);
        const float* brow = Bp + (size_t)(n0 + br) * ldb + k0 + bc;
        fb0 = *(const float4*)brow;
        if (LB4 == 2) fb1 = *(const float4*)(brow + 4);
    };

    auto sto = [&](int buf) {
        float va[8] = {fa0.x, fa0.y, fa0.z, fa0.w, fa1.x, fa1.y, fa1.z, fa1.w};
#pragma unroll
        for (int p = 0; p < 4; ++p) {
            float x0 = va[2 * p], x1 = va[2 * p + 1];
            __nv_bfloat16 h0 = __float2bfloat16(x0);
            __nv_bfloat16 h1 = __float2bfloat16(x1);
            __nv_bfloat16 l0 = __float2bfloat16(x0 - __bfloat162float(h0));
            __nv_bfloat16 l1 = __float2bfloat16(x1 - __bfloat162float(h1));
            __nv_bfloat162 ph; ph.x = h0; ph.y = h1;
            __nv_bfloat162 pl; pl.x = l0; pl.y = l1;
            *(__nv_bfloat162*)&Ah[buf][ar][ac + 2 * p] = ph;
            *(__nv_bfloat162*)&Al[buf][ar][ac + 2 * p] = pl;
        }
        float vb[8] = {fb0.x, fb0.y, fb0.z, fb0.w, fb1.x, fb1.y, fb1.z, fb1.w};
        constexpr int NP = LB4 * 2;
#pragma unroll
        for (int p = 0; p < NP; ++p) {
            float x0 = vb[2 * p], x1 = vb[2 * p + 1];
            __nv_bfloat16 h0 = __float2bfloat16(x0);
            __nv_bfloat16 h1 = __float2bfloat16(x1);
            __nv_bfloat16 l0 = __float2bfloat16(x0 - __bfloat162float(h0));
            __nv_bfloat16 l1 = __float2bfloat16(x1 - __bfloat162float(h1));
            __nv_bfloat162 ph; ph.x = h0; ph.y = h1;
            __nv_bfloat162 pl; pl.x = l0; pl.y = l1;
            *(__nv_bfloat162*)&Bh[buf][br][bc + 2 * p] = ph;
            *(__nv_bfloat162*)&Bl[buf][br][bc + 2 * p] = pl;
        }
    };

    auto comp = [&](int buf) {
        uint32_t ahr[MF][4], alr[MF][4], bhr[NF][2], blr[NF][2];
#pragma unroll
        for (int f = 0; f < MF; ++f) {
            int rbase = wm * (MF * 16) + f * 16 + g;
#pragma unroll
            for (int j = 0; j < 4; ++j) {
                int rr = rbase + (j & 1) * 8;
                int cc = 2 * t + (j >> 1) * 8;
                ahr[f][j] = *(const uint32_t*)&Ah[buf][rr][cc];
                alr[f][j] = *(const uint32_t*)&Al[buf][rr][cc];
            }
        }
#pragma unroll
        for (int nn = 0; nn < NF; ++nn) {
            int rb = wn * (NF * 8) + nn * 8 + g;
            bhr[nn][0] = *(const uint32_t*)&Bh[buf][rb][2 * t];
            bhr[nn][1] = *(const uint32_t*)&Bh[buf][rb][2 * t + 8];
            blr[nn][0] = *(const uint32_t*)&Bl[buf][rb][2 * t];
            blr[nn][1] = *(const uint32_t*)&Bl[buf][rb][2 * t + 8];
        }
#pragma unroll
        for (int f = 0; f < MF; ++f)
#pragma unroll
            for (int nn = 0; nn < NF; ++nn)
                mma16816(acc[f][nn], ahr[f][0], ahr[f][1], ahr[f][2], ahr[f][3],
                         bhr[nn][0], bhr[nn][1]);
#pragma unroll
        for (int f = 0; f < MF; ++f)
#pragma unroll
            for (int nn = 0; nn < NF; ++nn)
                mma16816(acc[f][nn], ahr[f][0], ahr[f][1], ahr[f][2], ahr[f][3],
                         blr[nn][0], blr[nn][1]);
#pragma unroll
        for (int f = 0; f < MF; ++f)
#pragma unroll
            for (int nn = 0; nn < NF; ++nn)
                mma16816(acc[f][nn], alr[f][0], alr[f][1], alr[f][2], alr[f][3],
                         bhr[nn][0], bhr[nn][1]);
    };

    fetch(0);
    sto(0);
    __syncthreads();
    const int nk = K / 16;
    int buf = 0;
    for (int ki = 0; ki < nk; ++ki) {
        bool more = (ki + 1 < nk);
        if (more) fetch((ki + 1) * 16);
        comp(buf);
        if (more) {
            sto(buf ^ 1);
            __syncthreads();
            buf ^= 1;
        }
    }

    // ---------------- epilogue ----------------
#pragma unroll
    for (int f = 0; f < MF; ++f) {
#pragma unroll
        for (int nn = 0; nn < NF; ++nn) {
#pragma unroll
            for (int i2 = 0; i2 < 2; ++i2) {
                int m = m0 + wm * (MF * 16) + f * 16 + g + i2 * 8;
                int n = n0 + wn * (NF * 8) + nn * 8 + 2 * t;
                float v0 = acc[f][nn][i2 * 2 + 0];
                float v1 = acc[f][nn][i2 * 2 + 1];

                if (MODE == 1) {
                    v0 += biasp[n]; v1 += biasp[n + 1];
                    float2 st = {v0, v1};
                    *(float2*)&Cg[(size_t)m * DMODEL + n] = st;
                } else if (MODE == 3) {
                    const int bidx = z / HEADS;
                    float mk0 = maskg[bidx * SEQ + n];
                    float mk1 = maskg[bidx * SEQ + n + 1];
                    float2 st;
                    st.x = (mk0 != 0.0f) ? -INFINITY : v0 * 0.125f;
                    st.y = (mk1 != 0.0f) ? -INFINITY : v1 * 0.125f;
                    *(float2*)&Cg[(long long)z * SEQ * SEQ + (size_t)m * SEQ + n] = st;
                } else if (MODE == 4) {
                    const int b = z / HEADS, h = z % HEADS;
                    float2 st = {v0, v1};
                    *(float2*)&Cg[((size_t)(b * SEQ + m)) * DMODEL + h * HDIM + n] = st;
                } else if (MODE == 5) {
                    v0 += biasp[n]; v1 += biasp[n + 1];
                    int b = m >> 11, s = m & 2047;
                    int h = n >> 6,  dh = n & 63;
                    if (z < 2) {
                        float2 st = {v0, v1};
                        *(float2*)&qa.C[z][(((size_t)(b * HEADS + h)) * SEQ + s) * HDIM + dh] = st;
                    } else {
                        qa.C[2][(((size_t)(b * HEADS + h)) * HDIM + dh + 0) * SEQ + s] = v0;
                        qa.C[2][(((size_t)(b * HEADS + h)) * HDIM + dh + 1) * SEQ + s] = v1;
                    }
                }
            }
        }
    }
}

// ---------------------------------------------------------------------------
// Row softmax in place: one block (256 thr) per row of 2048
// ---------------------------------------------------------------------------
__global__ void softmax_kernel(float* __restrict__ w)
{
    __shared__ float red[8];
    const size_t row = blockIdx.x;
    float* p = w + row * SEQ;
    const int tid = threadIdx.x;
    const int lane = tid & 31, wid = tid >> 5;

    float4 v0 = ((const float4*)p)[tid];
    float4 v1 = ((const float4*)p)[tid + 256];

    float mx = fmaxf(fmaxf(fmaxf(v0.x, v0.y), fmaxf(v0.z, v0.w)),
                     fmaxf(fmaxf(v1.x, v1.y), fmaxf(v1.z, v1.w)));
#pragma unroll
    for (int off = 16; off > 0; off >>= 1)
        mx = fmaxf(mx, __shfl_xor_sync(0xffffffffu, mx, off));
    if (lane == 0) red[wid] = mx;
    __syncthreads();
    if (tid == 0) {
        float m = red[0];
#pragma unroll
        for (int i = 1; i < 8; ++i) m = fmaxf(m, red[i]);
        red[0] = m;
    }
    __syncthreads();
    mx = red[0];

    float e[8];
    e[0] = __expf(v0.x - mx); e[1] = __expf(v0.y - mx);
    e[2] = __expf(v0.z - mx); e[3] = __expf(v0.w - mx);
    e[4] = __expf(v1.x - mx); e[5] = __expf(v1.y - mx);
    e[6] = __expf(v1.z - mx); e[7] = __expf(v1.w - mx);
    float sum = 0.0f;
#pragma unroll
    for (int i = 0; i < 8; ++i) sum += e[i];
#pragma unroll
    for (int off = 16; off > 0; off >>= 1)
        sum += __shfl_xor_sync(0xffffffffu, sum, off);
    __syncthreads();
    if (lane == 0) red[wid] = sum;
    __syncthreads();
    if (tid == 0) {
        float s = 0.0f;
#pragma unroll
        for (int i = 0; i < 8; ++i) s += red[i];
        red[0] = s;
    }
    __syncthreads();
    float inv = 1.0f / red[0];

    float4 o0, o1;
    o0.x = e[0] * inv; o0.y = e[1] * inv; o0.z = e[2] * inv; o0.w = e[3] * inv;
    o1.x = e[4] * inv; o1.y = e[5] * inv; o1.z = e[6] * inv; o1.w = e[7] * inv;
    ((float4*)p)[tid]       = o0;
    ((float4*)p)[tid + 256] = o1;
}

// ---------------------------------------------------------------------------
extern "C" void kernel_launch(void* const* d_in, const int* in_sizes, int n_in,
                              void* d_out, int out_size)
{
    const float* q    = (const float*)d_in[0];
    const float* k    = (const float*)d_in[1];
    const float* v    = (const float*)d_in[2];
    const float* mask = (const float*)d_in[3];
    const float* Wq   = (const float*)d_in[4];
    const float* bq   = (const float*)d_in[5];
    const float* Wk   = (const float*)d_in[6];
    const float* bk   = (const float*)d_in[7];
    const float* Wv   = (const float*)d_in[8];
    const float* bv   = (const float*)d_in[9];
    const float* Wo   = (const float*)d_in[10];
    const float* bo   = (const float*)d_in[11];

    float *p_qw, *p_kw, *p_vwT, *p_ctx, *p_wsc, *p_osc;
    cudaGetSymbolAddress((void**)&p_qw,  g_qw);
    cudaGetSymbolAddress((void**)&p_kw,  g_kw);
    cudaGetSymbolAddress((void**)&p_vwT, g_vwT);
    cudaGetSymbolAddress((void**)&p_ctx, g_ctx);
    cudaGetSymbolAddress((void**)&p_wsc, g_wscratch);
    cudaGetSymbolAddress((void**)&p_osc, g_oscratch);

    float* outp;
    float* wp;
    long long osz = (long long)out_size;
    if (osz >= OUT_ELEMS + W_ELEMS) {
        outp = (float*)d_out;
        wp   = (float*)d_out + OUT_ELEMS;
    } else if (osz == W_ELEMS) {
        wp   = (float*)d_out;
        outp = p_osc;
    } else {
        outp = (float*)d_out;
        wp   = p_wsc;
    }

    QKVArgs qa;
    qa.A[0] = q;  qa.A[1] = k;  qa.A[2] = v;
    qa.W[0] = Wq; qa.W[1] = Wk; qa.W[2] = Wv;
    qa.b[0] = bq; qa.b[1] = bk; qa.b[2] = bv;
    qa.C[0] = p_qw; qa.C[1] = p_kw; qa.C[2] = p_vwT;

    QKVArgs qa0 = {};

    // Fused Q/K/V projections (z = 0,1,2)
    mma_gemm<128, 4, 4, 2, 4, 5><<<dim3(ROWS / 128, DMODEL / 128, 3), 256>>>(
        nullptr, DMODEL, 0, nullptr, DMODEL, 0, nullptr, nullptr, nullptr, DMODEL, qa);

    // Scores: per (b,h): Q @ K^T * 0.125, masked, unnormalized -> wp
    mma_gemm<128, 4, 4, 2, 4, 3><<<dim3(SEQ / 128, SEQ / 128, BH), 256>>>(
        p_qw, HDIM, (long long)SEQ * HDIM,
        p_kw, HDIM, (long long)SEQ * HDIM,
        wp, nullptr, mask, HDIM, qa0);

    // Row softmax in place
    softmax_kernel<<<BH * SEQ, 256>>>(wp);

    // ctx = P @ V (via V^T): per (b,h): [2048,2048]x[64,2048]^T
    mma_gemm<64, 2, 4, 4, 2, 4><<<dim3(SEQ / 128, 1, BH), 256>>>(
        wp, SEQ, (long long)SEQ * SEQ,
        p_vwT, SEQ, (long long)HDIM * SEQ,
        p_ctx, nullptr, nullptr, SEQ, qa0);

    // Output projection
    mma_gemm<128, 4, 4, 2, 4, 1><<<dim3(ROWS / 128, DMODEL / 128, 1), 256>>>(
        p_ctx, DMODEL, 0, Wo, DMODEL, 0, outp, bo, nullptr, DMODEL, qa0);
}